// round 14
// baseline (speedup 1.0000x reference)
#include <cuda_runtime.h>
#include <math.h>

#define SQ   1024
#define HH   256
#define BBATCH 16
#define G4   1024   /* 4*H */

typedef unsigned long long ull;

// ---------------- scratch (static device globals: allocation-free) ----------
__device__ float g_xproj[BBATCH * SQ * G4];   // layer-0 input projection
__device__ float g_h0[BBATCH * SQ * HH];      // layer-0 hidden history (+ flags below)
__device__ float g_h1[BBATCH * SQ * HH];      // layer-1 hidden history
__device__ unsigned g_cnt0[BBATCH][SQ];       // h0[t] readiness flags (8 = ready)

// ---------------- helpers ----------------------------------------------------
__device__ __forceinline__ float warp_sum(float v) {
#pragma unroll
    for (int o = 16; o > 0; o >>= 1) v += __shfl_xor_sync(0xffffffffu, v, o);
    return v;
}
__device__ __forceinline__ float warp_max(float v) {
#pragma unroll
    for (int o = 16; o > 0; o >>= 1) v = fmaxf(v, __shfl_xor_sync(0xffffffffu, v, o));
    return v;
}
__device__ __forceinline__ unsigned smem_u32(const void* p) {
    unsigned a;
    asm("{ .reg .u64 t; cvta.to.shared.u64 t, %1; cvt.u32.u64 %0, t; }" : "=r"(a) : "l"(p));
    return a;
}
__device__ __forceinline__ unsigned ctarank() {
    unsigned r; asm("mov.u32 %0, %%cluster_ctarank;" : "=r"(r)); return r;
}
__device__ __forceinline__ void cluster_sync_() {
    asm volatile("barrier.cluster.arrive.aligned;\n\tbarrier.cluster.wait.aligned;" ::: "memory");
}
__device__ __forceinline__ unsigned mapa_u32(unsigned laddr, unsigned rank) {
    unsigned ra;
    asm("mapa.shared::cluster.u32 %0, %1, %2;" : "=r"(ra) : "r"(laddr), "r"(rank));
    return ra;
}
__device__ __forceinline__ void dsmem_st1(unsigned raddr, float v) {
    asm volatile("st.shared::cluster.b32 [%0], %1;"
                 :: "r"(raddr), "r"(__float_as_uint(v)) : "memory");
}
#define FMA2(acc, a, b) asm volatile("fma.rn.f32x2 %0, %1, %2, %0;" : "+l"(acc) : "l"(a), "l"(b))
__device__ __forceinline__ float2 unpack2(ull u) {
    float2 f; asm("mov.b64 {%0, %1}, %2;" : "=f"(f.x), "=f"(f.y) : "l"(u)); return f;
}
__device__ __forceinline__ ull pack2(float x, float y) {
    ull r; asm("mov.b64 %0, {%1, %2};" : "=l"(r) : "f"(x), "f"(y)); return r;
}
__device__ __forceinline__ float ex2f_(float x) {
    float r; asm("ex2.approx.ftz.f32 %0, %1;" : "=f"(r) : "f"(x)); return r;
}
__device__ __forceinline__ float rcpf_(float x) {
    float r; asm("rcp.approx.ftz.f32 %0, %1;" : "=f"(r) : "f"(x)); return r;
}
__device__ __forceinline__ float fast_sig(float x) {
    return rcpf_(1.f + ex2f_(-1.4426950408889634f * x));
}
__device__ __forceinline__ float fast_tanh(float x) {
    x = fminf(fmaxf(x, -15.f), 15.f);
    float u = ex2f_(2.8853900817779268f * x);
    return (u - 1.f) * rcpf_(u + 1.f);
}
__device__ __forceinline__ unsigned ld_acq(const unsigned* p) {
    unsigned v;
    asm volatile("ld.acquire.gpu.global.u32 %0, [%1];" : "=r"(v) : "l"(p) : "memory");
    return v;
}
__device__ __forceinline__ void red_add(unsigned* p, unsigned v) {
    asm volatile("red.global.add.u32 [%0], %1;" :: "l"(p), "r"(v) : "memory");
}
__device__ __forceinline__ void membar_gl_() { asm volatile("membar.gl;" ::: "memory"); }
__device__ __forceinline__ void stcg(float* p, float v) {
    asm volatile("st.global.cg.f32 [%0], %1;" :: "l"(p), "f"(v) : "memory");
}
__device__ __forceinline__ float2 ldcg2(const float* p) {
    float2 v;
    asm volatile("ld.global.cg.v2.f32 {%0, %1}, [%2];" : "=f"(v.x), "=f"(v.y) : "l"(p) : "memory");
    return v;
}

// ---------------- GEMM (layer-0 input projection only) ----------------------
// out[m,n] = sum_k X[m,k]*W[n,k] + b1[n] + b2[n]; M=16384, N=1024, K=32.
__global__ void __launch_bounds__(256)
gemm_xproj_kernel(const float* __restrict__ X, const float* __restrict__ W,
                  const float* __restrict__ b1, const float* __restrict__ b2,
                  int K)
{
    __shared__ __align__(16) float As[16][132];
    __shared__ __align__(16) float Bs[16][132];
    float* out = g_xproj;
    const int N = G4;

    int bm = blockIdx.y * 128, bn = blockIdx.x * 128;
    int tid = threadIdx.x;
    int lr = tid >> 2, lc = (tid & 3) << 2;
    int tm = (tid >> 4) << 3, tn = (tid & 15) << 3;

    ull acc[8][4];
#pragma unroll
    for (int i = 0; i < 8; i++)
#pragma unroll
        for (int j = 0; j < 4; j++) acc[i][j] = 0ull;

    for (int k0 = 0; k0 < K; k0 += 16) {
        float4 a0 = *(const float4*)&X[(size_t)(bm + lr) * K + k0 + lc];
        float4 a1 = *(const float4*)&X[(size_t)(bm + lr + 64) * K + k0 + lc];
        float4 w0 = *(const float4*)&W[(size_t)(bn + lr) * K + k0 + lc];
        float4 w1 = *(const float4*)&W[(size_t)(bn + lr + 64) * K + k0 + lc];
        __syncthreads();
        As[lc + 0][lr] = a0.x; As[lc + 1][lr] = a0.y; As[lc + 2][lr] = a0.z; As[lc + 3][lr] = a0.w;
        As[lc + 0][lr + 64] = a1.x; As[lc + 1][lr + 64] = a1.y; As[lc + 2][lr + 64] = a1.z; As[lc + 3][lr + 64] = a1.w;
        Bs[lc + 0][lr] = w0.x; Bs[lc + 1][lr] = w0.y; Bs[lc + 2][lr] = w0.z; Bs[lc + 3][lr] = w0.w;
        Bs[lc + 0][lr + 64] = w1.x; Bs[lc + 1][lr + 64] = w1.y; Bs[lc + 2][lr + 64] = w1.z; Bs[lc + 3][lr + 64] = w1.w;
        __syncthreads();
#pragma unroll
        for (int k = 0; k < 16; k++) {
            float av[8], bv[8];
            *(float4*)&av[0] = *(const float4*)&As[k][tm];
            *(float4*)&av[4] = *(const float4*)&As[k][tm + 4];
            *(float4*)&bv[0] = *(const float4*)&Bs[k][tn];
            *(float4*)&bv[4] = *(const float4*)&Bs[k][tn + 4];
            ull b2v[4];
#pragma unroll
            for (int j = 0; j < 4; j++) b2v[j] = pack2(bv[2 * j], bv[2 * j + 1]);
#pragma unroll
            for (int i = 0; i < 8; i++) {
                ull a2 = pack2(av[i], av[i]);
#pragma unroll
                for (int j = 0; j < 4; j++)
                    FMA2(acc[i][j], a2, b2v[j]);
            }
        }
    }
    float bias8[8];
#pragma unroll
    for (int j = 0; j < 8; j++) bias8[j] = b1[bn + tn + j] + b2[bn + tn + j];
#pragma unroll
    for (int i = 0; i < 8; i++) {
        float o[8];
#pragma unroll
        for (int j = 0; j < 4; j++) {
            float2 e = unpack2(acc[i][j]);
            o[2 * j] = e.x + bias8[2 * j];
            o[2 * j + 1] = e.y + bias8[2 * j + 1];
        }
        float* dst = &out[(size_t)(bm + tm + i) * N + bn + tn];
        *(float4*)&dst[0] = make_float4(o[0], o[1], o[2], o[3]);
        *(float4*)&dst[4] = make_float4(o[4], o[5], o[6], o[7]);
    }
}

// ---------------- Pipelined 2-layer LSTM recurrence --------------------------
// ONE launch, 128 CTAs = 16 clusters of 8 (all co-resident, 1 wave).
//   clusters 0-7  : layer 0, cluster c -> samples 2c, 2c+1 (R7 push protocol)
//   clusters 8-15 : layer 1, trailing layer 0 by ~1 step.
// Layer 0 publishes h0[t] via st.cg + membar.gl + red.add flag (R11 pattern).
// Layer 1 per step: bounded-poll flag, stage h0[t] from L2, compute
// xproj1[t] = W_ih1·h0[t] from an smem-resident W_ih1 slice (dynamic smem,
// pitch 260 floats -> conflict-free LDS.128), folded into the same FFMA2
// accumulators as the recurrent matvec. Within-cluster protocol = R7 verbatim.
__global__ void __launch_bounds__(256, 1)
lstm_pipe_kernel(const float* __restrict__ Whh0, const float* __restrict__ Whh1,
                 const float* __restrict__ Wih1, const float* __restrict__ bih1,
                 const float* __restrict__ bhh1)
{
    extern __shared__ float sW[];                      // layer1: [128][260] W_ih slice
    __shared__ __align__(16) float sh_h[2][2][HH];     // parity, sample
    __shared__ __align__(16) float sh_part[128][2][2]; // r, half, sample
    __shared__ __align__(16) float sh_h0[2][HH];       // layer1: h0[t] staging

    int tid = threadIdx.x;
    int r = tid & 127, half = tid >> 7;
    int wid = tid >> 5, lane = tid & 31;
    unsigned rank = ctarank();
    int cid = blockIdx.x >> 3;
    int layer = (cid >= 8);
    int pair = cid & 7;
    int b0 = pair * 2, b1 = b0 + 1;
    int gt = r >> 5, uo = r & 31;
    int G = gt * HH + (int)rank * 32 + uo;

    const float* Whh = layer ? Whh1 : Whh0;
    ull w[64];
    {
        const ull* wp = reinterpret_cast<const ull*>(Whh + (size_t)G * HH + half * 128);
#pragma unroll
        for (int i = 0; i < 64; i++) w[i] = wp[i];
    }

    float biasg = 0.f;
    if (layer) {
        if (half == 0) biasg = bih1[G] + bhh1[G];
        const float4* src = (const float4*)(Wih1 + (size_t)G * HH + half * 128);
        float4* dst = (float4*)&sW[r * 260 + half * 128];
#pragma unroll
        for (int i = 0; i < 32; i++) dst[i] = src[i];
    }

    for (int i = tid; i < 2 * 2 * HH; i += 256) ((float*)sh_h)[i] = 0.f;
    __syncthreads();
    cluster_sync_();   // zeroed buffers visible cluster-wide

    int unit = (int)rank * 32 + lane;
    unsigned rd00 = mapa_u32(smem_u32(&sh_h[0][0][unit]), (unsigned)wid);
    unsigned rd01 = mapa_u32(smem_u32(&sh_h[0][1][unit]), (unsigned)wid);
    unsigned rd10 = mapa_u32(smem_u32(&sh_h[1][0][unit]), (unsigned)wid);
    unsigned rd11 = mapa_u32(smem_u32(&sh_h[1][1][unit]), (unsigned)wid);

    const float* xp0 = g_xproj + (size_t)b0 * SQ * G4 + G;
    const float* xp1 = g_xproj + (size_t)b1 * SQ * G4 + G;
    float xv0 = 0.f, xv1 = 0.f;
    if (!layer && half == 0) { xv0 = xp0[0]; xv1 = xp1[0]; }

    float c0 = 0.f, c1 = 0.f;
    int p = 0, broken = 0;
    float* h0w0 = g_h0 + (size_t)b0 * SQ * HH + unit;
    float* h0w1 = g_h0 + (size_t)b1 * SQ * HH + unit;
    float* h1w0 = g_h1 + (size_t)b0 * SQ * HH + unit;
    float* h1w1 = g_h1 + (size_t)b1 * SQ * HH + unit;

    for (int t = 0; t < SQ; t++) {
        ull a00 = 0, a01 = 0, a02 = 0, a03 = 0;
        ull a10 = 0, a11 = 0, a12 = 0, a13 = 0;

        if (layer) {
            // bounded-wait for h0[t] of both samples (flags reach 8)
            if (tid < 2) {
                const unsigned* f = &g_cnt0[tid ? b1 : b0][t];
                int cap = broken ? 8 : 100000;
                int ok = 0;
                for (int i = 0; i < cap; i++)
                    if (ld_acq(f) >= 8u) { ok = 1; break; }
                if (!ok) broken = 1;
            }
            __syncthreads();
            // stage h0[t] (both samples) into smem
            {
                int s = tid >> 7;
                int k = (tid & 127) * 2;
                const float* src = g_h0 + (size_t)(s ? b1 : b0) * SQ * HH + (size_t)t * HH + k;
                float2 v = ldcg2(src);
                sh_h0[s][k] = v.x; sh_h0[s][k + 1] = v.y;
            }
            __syncthreads();
            // xproj accumulation from smem-resident W_ih1 slice
            const ulonglong2* wih = (const ulonglong2*)&sW[r * 260 + half * 128];
            const ulonglong2* q0 = (const ulonglong2*)&sh_h0[0][half * 128];
            const ulonglong2* q1 = (const ulonglong2*)&sh_h0[1][half * 128];
#pragma unroll
            for (int q = 0; q < 32; q += 2) {
                ulonglong2 wv0 = wih[q], wv1 = wih[q + 1];
                ulonglong2 h00 = q0[q], h01 = q0[q + 1];
                ulonglong2 h10 = q1[q], h11 = q1[q + 1];
                FMA2(a00, wv0.x, h00.x); FMA2(a01, wv0.y, h00.y);
                FMA2(a02, wv1.x, h01.x); FMA2(a03, wv1.y, h01.y);
                FMA2(a10, wv0.x, h10.x); FMA2(a11, wv0.y, h10.y);
                FMA2(a12, wv1.x, h11.x); FMA2(a13, wv1.y, h11.y);
            }
        }

        // recurrent matvec (both samples) from pushed sh_h[p]
        {
            const ulonglong2* h2a = (const ulonglong2*)&sh_h[p][0][half * 128];
            const ulonglong2* h2b = (const ulonglong2*)&sh_h[p][1][half * 128];
#pragma unroll
            for (int q = 0; q < 32; q += 2) {
                ulonglong2 hv0 = h2a[q], hv1 = h2a[q + 1];
                ulonglong2 g0 = h2b[q], g1 = h2b[q + 1];
                FMA2(a00, w[2 * q + 0], hv0.x); FMA2(a01, w[2 * q + 1], hv0.y);
                FMA2(a02, w[2 * q + 2], hv1.x); FMA2(a03, w[2 * q + 3], hv1.y);
                FMA2(a10, w[2 * q + 0], g0.x);  FMA2(a11, w[2 * q + 1], g0.y);
                FMA2(a12, w[2 * q + 2], g1.x);  FMA2(a13, w[2 * q + 3], g1.y);
            }
        }
        float2 e0 = unpack2(a00), e1 = unpack2(a01), e2 = unpack2(a02), e3 = unpack2(a03);
        float s0 = ((e0.x + e0.y) + (e1.x + e1.y)) + ((e2.x + e2.y) + (e3.x + e3.y));
        float2 d0 = unpack2(a10), d1 = unpack2(a11), d2 = unpack2(a12), d3 = unpack2(a13);
        float s1 = ((d0.x + d0.y) + (d1.x + d1.y)) + ((d2.x + d2.y) + (d3.x + d3.y));
        if (half == 0) {
            if (layer) { s0 += biasg; s1 += biasg; }
            else       { s0 += xv0;  s1 += xv1; }
        }
        *(float2*)&sh_part[r][half][0] = make_float2(s0, s1);
        __syncthreads();

        // prefetch next x (layer 0)
        float xn0 = 0.f, xn1 = 0.f;
        if (!layer && half == 0 && t + 1 < SQ) {
            xn0 = xp0[(size_t)(t + 1) * G4];
            xn1 = xp1[(size_t)(t + 1) * G4];
        }

        // gates: unit = lane, both samples, redundant in all warps
        float4 fi = *(const float4*)&sh_part[lane][0][0];
        float4 ff = *(const float4*)&sh_part[32 + lane][0][0];
        float4 fg = *(const float4*)&sh_part[64 + lane][0][0];
        float4 fo = *(const float4*)&sh_part[96 + lane][0][0];
        float iv0 = fast_sig(fi.x + fi.z), iv1 = fast_sig(fi.y + fi.w);
        float fv0 = fast_sig(ff.x + ff.z), fv1 = fast_sig(ff.y + ff.w);
        float gv0 = fast_tanh(fg.x + fg.z), gv1 = fast_tanh(fg.y + fg.w);
        float ov0 = fast_sig(fo.x + fo.z), ov1 = fast_sig(fo.y + fo.w);
        c0 = fv0 * c0 + iv0 * gv0;
        c1 = fv1 * c1 + iv1 * gv1;
        float hv0 = ov0 * fast_tanh(c0);
        float hv1 = ov1 * fast_tanh(c1);

        // push (R7 style): warp w -> dest CTA w, write buffer p^1
        if (p) { dsmem_st1(rd00, hv0); dsmem_st1(rd01, hv1); }
        else   { dsmem_st1(rd10, hv0); dsmem_st1(rd11, hv1); }

        if (wid == 0) {
            if (!layer) {
                stcg(h0w0 + (size_t)t * HH, hv0);
                stcg(h0w1 + (size_t)t * HH, hv1);
                __syncwarp();
                if (lane == 0) {
                    membar_gl_();
                    red_add(&g_cnt0[b0][t], 1u);
                    red_add(&g_cnt0[b1][t], 1u);
                }
            } else {
                h1w0[(size_t)t * HH] = hv0;
                h1w1[(size_t)t * HH] = hv1;
            }
        }
        xv0 = xn0; xv1 = xn1;
        cluster_sync_();   // releases DSMEM pushes + protects smem reuse (R7-proven)
        p ^= 1;
    }
}

// ---------------- attention (last query only) + heads -----------------------
// One CTA per batch sample; also resets the pipeline flags for graph replays.
__global__ void __launch_bounds__(256)
head_kernel(const float* __restrict__ Wq, const float* __restrict__ bq,
            const float* __restrict__ Wk, const float* __restrict__ bk,
            const float* __restrict__ Wv, const float* __restrict__ bv,
            const float* __restrict__ Wo, const float* __restrict__ bo,
            const float* __restrict__ Wm, const float* __restrict__ bm,
            const float* __restrict__ Wvr, const float* __restrict__ bvr,
            float* __restrict__ outp)
{
    extern __shared__ float sm[];
    float* sh_hlast  = sm;            // 256
    float* sh_q      = sm + 256;      // 256
    float* sh_w      = sm + 512;      // 8*256
    float* sh_cc     = sm + 2560;     // 8 (+pad)
    float* sh_scores = sm + 2576;     // 8*1024
    float* sh_hbar   = sm + 10768;    // 8*256
    float* sh_attn   = sm + 12816;    // 256
    float* sh_y      = sm + 13072;    // 256

    int b = blockIdx.x, tid = threadIdx.x, wid = tid >> 5, lane = tid & 31;
    const float* hb = g_h1 + (size_t)b * SQ * HH;

    // reset h0 readiness flags for the next graph replay
    for (int i = tid; i < SQ; i += 256) g_cnt0[b][i] = 0u;

    sh_hlast[tid] = hb[(size_t)(SQ - 1) * HH + tid];
    __syncthreads();

    for (int j = 0; j < 32; j++) {
        int n = wid * 32 + j;
        float acc = 0.f;
#pragma unroll
        for (int i = 0; i < 8; i++)
            acc += Wq[(size_t)n * HH + lane + 32 * i] * sh_hlast[lane + 32 * i];
        acc = warp_sum(acc);
        if (lane == 0) sh_q[n] = acc + bq[n];
    }
    __syncthreads();

    {
        float v = sh_q[wid * 32 + lane] * bk[wid * 32 + lane];
        v = warp_sum(v);
        if (lane == 0) sh_cc[wid] = v;
    }
    {
        float acc[8] = {0.f, 0.f, 0.f, 0.f, 0.f, 0.f, 0.f, 0.f};
        for (int rr = 0; rr < HH; rr++) {
            float wkv = Wk[(size_t)rr * HH + tid];
            acc[rr >> 5] += wkv * sh_q[rr];
        }
#pragma unroll
        for (int h = 0; h < 8; h++) sh_w[h * HH + tid] = acc[h];
    }
    __syncthreads();

    const float L2D = -0.07400058144377693f;      // log2(0.95)
    const float ISQ = 0.17677669529663687f;       // 1/sqrt(32)
    for (int t = 0; t < SQ; t++) {
        const float* hr = hb + (size_t)t * HH;
        float acc = 0.f;
#pragma unroll
        for (int i = 0; i < 8; i++)
            acc += sh_w[wid * HH + lane + 32 * i] * hr[lane + 32 * i];
        acc = warp_sum(acc);
        if (lane == 0) {
            float sc = (acc + sh_cc[wid]) * ISQ;
            sc *= exp2f((float)(SQ - 1 - t) * L2D);
            sh_scores[wid * SQ + t] = sc;
        }
    }
    __syncwarp();

    float mx = -1e30f;
    for (int t = lane; t < SQ; t += 32) mx = fmaxf(mx, sh_scores[wid * SQ + t]);
    mx = warp_max(mx);
    float sum = 0.f;
    for (int t = lane; t < SQ; t += 32) {
        float e = __expf(sh_scores[wid * SQ + t] - mx);
        sh_scores[wid * SQ + t] = e;
        sum += e;
    }
    sum = warp_sum(sum);
    float inv = 1.f / sum;
    for (int t = lane; t < SQ; t += 32) sh_scores[wid * SQ + t] *= inv;
    __syncwarp();

    float hb8[8] = {0.f, 0.f, 0.f, 0.f, 0.f, 0.f, 0.f, 0.f};
    for (int t = 0; t < SQ; t++) {
        float pv = sh_scores[wid * SQ + t];
        const float* hr = hb + (size_t)t * HH;
#pragma unroll
        for (int i = 0; i < 8; i++) hb8[i] += pv * hr[lane + 32 * i];
    }
#pragma unroll
    for (int i = 0; i < 8; i++) sh_hbar[wid * HH + lane + 32 * i] = hb8[i];
    __syncwarp();

    for (int d = 0; d < 32; d++) {
        int row = wid * 32 + d;
        float acc = 0.f;
#pragma unroll
        for (int i = 0; i < 8; i++)
            acc += Wv[(size_t)row * HH + lane + 32 * i] * sh_hbar[wid * HH + lane + 32 * i];
        acc = warp_sum(acc);
        if (lane == 0) sh_attn[row] = acc + bv[row];
    }
    __syncthreads();

    for (int j = 0; j < 32; j++) {
        int n = wid * 32 + j;
        float acc = 0.f;
#pragma unroll
        for (int i = 0; i < 8; i++)
            acc += Wo[(size_t)n * HH + lane + 32 * i] * sh_attn[lane + 32 * i];
        acc = warp_sum(acc);
        if (lane == 0) sh_y[n] = acc + bo[n];
    }
    __syncthreads();

    if (tid < 5) {
        float a = 0.f;
        for (int k = 0; k < HH; k++) a += Wm[tid * HH + k] * sh_y[k];
        outp[b * 5 + tid] = a + bm[tid];
    } else if (tid >= 32 && tid < 37) {
        int j = tid - 32;
        float a = 0.f;
        for (int k = 0; k < HH; k++) a += Wvr[j * HH + k] * sh_y[k];
        outp[BBATCH * 5 + b * 5 + j] = a + bvr[j];
    }
}

// ---------------- launch ----------------------------------------------------
extern "C" void kernel_launch(void* const* d_in, const int* in_sizes, int n_in,
                              void* d_out, int out_size)
{
    const float* x    = (const float*)d_in[0];
    const float* Wih0 = (const float*)d_in[1];
    const float* Whh0 = (const float*)d_in[2];
    const float* bih0 = (const float*)d_in[3];
    const float* bhh0 = (const float*)d_in[4];
    const float* Wih1 = (const float*)d_in[5];
    const float* Whh1 = (const float*)d_in[6];
    const float* bih1 = (const float*)d_in[7];
    const float* bhh1 = (const float*)d_in[8];
    const float* Wq   = (const float*)d_in[9];
    const float* bq   = (const float*)d_in[10];
    const float* Wk   = (const float*)d_in[11];
    const float* bk   = (const float*)d_in[12];
    const float* Wv   = (const float*)d_in[13];
    const float* bv   = (const float*)d_in[14];
    const float* Wo   = (const float*)d_in[15];
    const float* bo   = (const float*)d_in[16];
    const float* Wm   = (const float*)d_in[17];
    const float* bm   = (const float*)d_in[18];
    const float* Wvr  = (const float*)d_in[19];
    const float* bvr  = (const float*)d_in[20];
    float* outp = (float*)d_out;

    (void)in_sizes; (void)n_in; (void)out_size;

    const int DYN_SMEM = 128 * 260 * 4;   // 133120 B: W_ih1 slice

    cudaFuncSetAttribute(head_kernel, cudaFuncAttributeMaxDynamicSharedMemorySize, 13328 * 4);
    cudaFuncSetAttribute(lstm_pipe_kernel, cudaFuncAttributeMaxDynamicSharedMemorySize, DYN_SMEM);

    // layer 0 input projection: x (16384 x 32) @ W_ih0^T + b_ih0 + b_hh0
    dim3 ggrid(8, 128);
    gemm_xproj_kernel<<<ggrid, 256>>>(x, Wih0, bih0, bhh0, 32);

    // pipelined both-layer recurrence: 128 CTAs = 16 clusters of 8
    cudaLaunchConfig_t cfg = {};
    cfg.gridDim = dim3(128, 1, 1);
    cfg.blockDim = dim3(256, 1, 1);
    cfg.dynamicSmemBytes = DYN_SMEM;
    cudaLaunchAttribute at[1];
    at[0].id = cudaLaunchAttributeClusterDimension;
    at[0].val.clusterDim.x = 8;
    at[0].val.clusterDim.y = 1;
    at[0].val.clusterDim.z = 1;
    cfg.attrs = at;
    cfg.numAttrs = 1;
    cfg.stream = 0;
    cudaLaunchKernelEx(&cfg, lstm_pipe_kernel, Whh0, Whh1, Wih1, bih1, bhh1);

    // decayed attention on last query + output heads (also resets flags)
    head_kernel<<<BBATCH, 256, 13328 * 4>>>(Wq, bq, Wk, bk, Wv, bv, Wo, bo,
                                            Wm, bm, Wvr, bvr, outp);
}

// round 15
// speedup vs baseline: 1.4862x; 1.4862x over previous
#include <cuda_runtime.h>
#include <math.h>

#define SQ   1024
#define HH   256
#define BBATCH 16
#define G4   1024   /* 4*H */

typedef unsigned long long ull;

// ---------------- scratch (static device globals: allocation-free) ----------
__device__ float g_xproj[BBATCH * SQ * G4];   // 64 MB, reused for both layers
__device__ float g_h0[BBATCH * SQ * HH];      // 16 MB
__device__ float g_h1[BBATCH * SQ * HH];      // 16 MB

// ---------------- helpers ----------------------------------------------------
__device__ __forceinline__ float warp_sum(float v) {
#pragma unroll
    for (int o = 16; o > 0; o >>= 1) v += __shfl_xor_sync(0xffffffffu, v, o);
    return v;
}
__device__ __forceinline__ float warp_max(float v) {
#pragma unroll
    for (int o = 16; o > 0; o >>= 1) v = fmaxf(v, __shfl_xor_sync(0xffffffffu, v, o));
    return v;
}
__device__ __forceinline__ unsigned smem_u32(const void* p) {
    unsigned a;
    asm("{ .reg .u64 t; cvta.to.shared.u64 t, %1; cvt.u32.u64 %0, t; }" : "=r"(a) : "l"(p));
    return a;
}
__device__ __forceinline__ unsigned ctarank() {
    unsigned r; asm("mov.u32 %0, %%cluster_ctarank;" : "=r"(r)); return r;
}
__device__ __forceinline__ void cluster_sync_() {
    asm volatile("barrier.cluster.arrive.aligned;\n\tbarrier.cluster.wait.aligned;" ::: "memory");
}
__device__ __forceinline__ void cluster_arrive_() {
    asm volatile("barrier.cluster.arrive.aligned;" ::: "memory");
}
__device__ __forceinline__ void cluster_wait_() {
    asm volatile("barrier.cluster.wait.aligned;" ::: "memory");
}
__device__ __forceinline__ unsigned mapa_u32(unsigned laddr, unsigned rank) {
    unsigned ra;
    asm("mapa.shared::cluster.u32 %0, %1, %2;" : "=r"(ra) : "r"(laddr), "r"(rank));
    return ra;
}
__device__ __forceinline__ void dsmem_st_v4(unsigned raddr, float a, float b, float c, float d) {
    asm volatile("st.shared::cluster.v4.b32 [%0], {%1, %2, %3, %4};"
                 :: "r"(raddr), "r"(__float_as_uint(a)), "r"(__float_as_uint(b)),
                    "r"(__float_as_uint(c)), "r"(__float_as_uint(d)) : "memory");
}
#define FMA2(acc, a, b) asm volatile("fma.rn.f32x2 %0, %1, %2, %0;" : "+l"(acc) : "l"(a), "l"(b))
__device__ __forceinline__ float2 unpack2(ull u) {
    float2 f; asm("mov.b64 {%0, %1}, %2;" : "=f"(f.x), "=f"(f.y) : "l"(u)); return f;
}
__device__ __forceinline__ ull pack2(float x, float y) {
    ull r; asm("mov.b64 %0, {%1, %2};" : "=l"(r) : "f"(x), "f"(y)); return r;
}
__device__ __forceinline__ float ex2f_(float x) {
    float r; asm("ex2.approx.ftz.f32 %0, %1;" : "=f"(r) : "f"(x)); return r;
}
__device__ __forceinline__ float rcpf_(float x) {
    float r; asm("rcp.approx.ftz.f32 %0, %1;" : "=f"(r) : "f"(x)); return r;
}
__device__ __forceinline__ float fast_sig(float x) {
    return rcpf_(1.f + ex2f_(-1.4426950408889634f * x));
}
__device__ __forceinline__ float fast_tanh(float x) {
    x = fminf(fmaxf(x, -15.f), 15.f);
    float u = ex2f_(2.8853900817779268f * x);
    return (u - 1.f) * rcpf_(u + 1.f);
}

// ---------------- GEMM: out[m,n] = sum_k X[m,k]*W[n,k] + b1[n] + b2[n] ------
// M=16384, N=1024 fixed; K in {32, 256}. 128x128 block tile, 8x8 per thread,
// packed fma.rn.f32x2 inner product.
__global__ void __launch_bounds__(256)
gemm_xproj_kernel(const float* __restrict__ Xext, const float* __restrict__ W,
                  const float* __restrict__ b1, const float* __restrict__ b2,
                  int K, int use_h0)
{
    __shared__ __align__(16) float As[16][132];
    __shared__ __align__(16) float Bs[16][132];
    const float* X = use_h0 ? g_h0 : Xext;
    float* out = g_xproj;
    const int N = G4;

    int bm = blockIdx.y * 128, bn = blockIdx.x * 128;
    int tid = threadIdx.x;
    int lr = tid >> 2, lc = (tid & 3) << 2;
    int tm = (tid >> 4) << 3, tn = (tid & 15) << 3;

    ull acc[8][4];
#pragma unroll
    for (int i = 0; i < 8; i++)
#pragma unroll
        for (int j = 0; j < 4; j++) acc[i][j] = 0ull;

    for (int k0 = 0; k0 < K; k0 += 16) {
        float4 a0 = *(const float4*)&X[(size_t)(bm + lr) * K + k0 + lc];
        float4 a1 = *(const float4*)&X[(size_t)(bm + lr + 64) * K + k0 + lc];
        float4 w0 = *(const float4*)&W[(size_t)(bn + lr) * K + k0 + lc];
        float4 w1 = *(const float4*)&W[(size_t)(bn + lr + 64) * K + k0 + lc];
        __syncthreads();
        As[lc + 0][lr] = a0.x; As[lc + 1][lr] = a0.y; As[lc + 2][lr] = a0.z; As[lc + 3][lr] = a0.w;
        As[lc + 0][lr + 64] = a1.x; As[lc + 1][lr + 64] = a1.y; As[lc + 2][lr + 64] = a1.z; As[lc + 3][lr + 64] = a1.w;
        Bs[lc + 0][lr] = w0.x; Bs[lc + 1][lr] = w0.y; Bs[lc + 2][lr] = w0.z; Bs[lc + 3][lr] = w0.w;
        Bs[lc + 0][lr + 64] = w1.x; Bs[lc + 1][lr + 64] = w1.y; Bs[lc + 2][lr + 64] = w1.z; Bs[lc + 3][lr + 64] = w1.w;
        __syncthreads();
#pragma unroll
        for (int k = 0; k < 16; k++) {
            float av[8], bv[8];
            *(float4*)&av[0] = *(const float4*)&As[k][tm];
            *(float4*)&av[4] = *(const float4*)&As[k][tm + 4];
            *(float4*)&bv[0] = *(const float4*)&Bs[k][tn];
            *(float4*)&bv[4] = *(const float4*)&Bs[k][tn + 4];
            ull b2v[4];
#pragma unroll
            for (int j = 0; j < 4; j++) b2v[j] = pack2(bv[2 * j], bv[2 * j + 1]);
#pragma unroll
            for (int i = 0; i < 8; i++) {
                ull a2 = pack2(av[i], av[i]);
#pragma unroll
                for (int j = 0; j < 4; j++)
                    FMA2(acc[i][j], a2, b2v[j]);
            }
        }
    }
    float bias8[8];
#pragma unroll
    for (int j = 0; j < 8; j++) bias8[j] = b1[bn + tn + j] + b2[bn + tn + j];
#pragma unroll
    for (int i = 0; i < 8; i++) {
        float o[8];
#pragma unroll
        for (int j = 0; j < 4; j++) {
            float2 e = unpack2(acc[i][j]);
            o[2 * j] = e.x + bias8[2 * j];
            o[2 * j + 1] = e.y + bias8[2 * j + 1];
        }
        float* dst = &out[(size_t)(bm + tm + i) * N + bn + tn];
        *(float4*)&dst[0] = make_float4(o[0], o[1], o[2], o[3]);
        *(float4*)&dst[4] = make_float4(o[4], o[5], o[6], o[7]);
    }
}

// ---------------- LSTM recurrence: 8-CTA cluster per batch sample ----------
// R7 protocol (best measured: cluster.sync per step, push model) with two
// micro-deltas inside the same semantics:
//  1. v4-packed DSMEM pushes: shfl-pack 4 consecutive units into lanes 0-7,
//     which issue st.shared::cluster.v4 (64 remote transactions/CTA/step
//     instead of 256 scalar) -> less store drain inside the barrier.
//  2. Split barrier: arrive right after the pushes; hout STG and x prefetch
//     live in the arrive->wait gap (skew window) instead of after full sync.
// Ordering: arrive releases the pushes, wait acquires peers' pushes — same
// guarantees as the monolithic cluster.sync in R7.
__global__ void __launch_bounds__(256, 1)
lstm_rec_kernel(const float* __restrict__ Whh, int layer)
{
    __shared__ __align__(16) float sh_h[2][HH];
    __shared__ __align__(8) float sh_part[128][2];

    float* hout = layer ? g_h1 : g_h0;
    int tid = threadIdx.x;
    int r = tid & 127;
    int half = tid >> 7;
    int wid = tid >> 5, lane = tid & 31;
    unsigned rank = ctarank();
    int b = blockIdx.x >> 3;
    int gt = r >> 5, uo = r & 31;
    int G = gt * HH + (int)rank * 32 + uo;

    ull w[64];
    {
        const ull* wp = reinterpret_cast<const ull*>(Whh + (size_t)G * HH + half * 128);
#pragma unroll
        for (int i = 0; i < 64; i++) w[i] = wp[i];
    }

    sh_h[0][tid & 255] = 0.f;
    sh_h[1][tid & 255] = 0.f;
    __syncthreads();
    cluster_sync_();   // zeroed buffers visible cluster-wide

    // warp w services destination CTA w; lanes 0-7 store 4 consecutive units
    unsigned dest = (unsigned)wid;
    unsigned rdst0 = mapa_u32(smem_u32(&sh_h[0][(int)rank * 32 + 4 * (lane & 7)]), dest);
    unsigned rdst1 = mapa_u32(smem_u32(&sh_h[1][(int)rank * 32 + 4 * (lane & 7)]), dest);

    const float* xp = g_xproj + (size_t)b * SQ * G4 + G;
    float xv = (half == 0) ? xp[0] : 0.f;
    float creg = 0.f;

    int p = 0;
    for (int t = 0; t < SQ; t++) {
        // matvec: 32 LDS.128 + 64 FFMA2 (warp-uniform broadcast loads)
        const ulonglong2* h2 = reinterpret_cast<const ulonglong2*>(&sh_h[p][half * 128]);
        ull a0 = 0ull, a1 = 0ull, a2 = 0ull, a3 = 0ull;
#pragma unroll
        for (int q = 0; q < 32; q += 2) {
            ulonglong2 hv0 = h2[q];
            ulonglong2 hv1 = h2[q + 1];
            FMA2(a0, w[2 * q + 0], hv0.x);
            FMA2(a1, w[2 * q + 1], hv0.y);
            FMA2(a2, w[2 * q + 2], hv1.x);
            FMA2(a3, w[2 * q + 3], hv1.y);
        }
        float2 f0 = unpack2(a0), f1 = unpack2(a1), f2 = unpack2(a2), f3 = unpack2(a3);
        float s = ((f0.x + f0.y) + (f1.x + f1.y)) + ((f2.x + f2.y) + (f3.x + f3.y));
        sh_part[r][half] = (half == 0) ? (s + xv) : s;
        __syncthreads();

        // gates: every warp computes all 32 of this CTA's units (lane = unit)
        float2 pi = *(const float2*)sh_part[lane];
        float2 pf = *(const float2*)sh_part[32 + lane];
        float2 pg = *(const float2*)sh_part[64 + lane];
        float2 po = *(const float2*)sh_part[96 + lane];
        float iv = fast_sig(pi.x + pi.y);
        float fv = fast_sig(pf.x + pf.y);
        float gv = fast_tanh(pg.x + pg.y);
        float ov = fast_sig(po.x + po.y);
        creg = fv * creg + iv * gv;
        float hv = ov * fast_tanh(creg);

        // shfl-pack 4 consecutive units into lanes 0-7, push as one v4 store
        float v0 = __shfl_sync(0xffffffffu, hv, (lane * 4 + 0) & 31);
        float v1 = __shfl_sync(0xffffffffu, hv, (lane * 4 + 1) & 31);
        float v2 = __shfl_sync(0xffffffffu, hv, (lane * 4 + 2) & 31);
        float v3 = __shfl_sync(0xffffffffu, hv, (lane * 4 + 3) & 31);

        if (lane < 8)
            dsmem_st_v4(p ? rdst0 : rdst1, v0, v1, v2, v3);   // write buffer = p^1

        cluster_arrive_();   // releases the pushes; skew window opens

        // gap work: history store + next-x prefetch (purely local)
        if (wid == 0 && lane < 8) {
            float* gp = &hout[((size_t)b * SQ + t) * HH + (int)rank * 32 + 4 * lane];
            *(float4*)gp = make_float4(v0, v1, v2, v3);
        }
        float xnext = (half == 0 && t + 1 < SQ) ? xp[(size_t)(t + 1) * G4] : 0.f;
        xv = xnext;

        cluster_wait_();     // acquires peers' pushes; also full CTA barrier
        p ^= 1;
    }
}

// ---------------- attention (last query only) + heads -----------------------
// One CTA per batch sample, 256 threads, warp w == head w.
__global__ void __launch_bounds__(256)
head_kernel(const float* __restrict__ Wq, const float* __restrict__ bq,
            const float* __restrict__ Wk, const float* __restrict__ bk,
            const float* __restrict__ Wv, const float* __restrict__ bv,
            const float* __restrict__ Wo, const float* __restrict__ bo,
            const float* __restrict__ Wm, const float* __restrict__ bm,
            const float* __restrict__ Wvr, const float* __restrict__ bvr,
            float* __restrict__ outp)
{
    extern __shared__ float sm[];
    float* sh_hlast  = sm;            // 256
    float* sh_q      = sm + 256;      // 256
    float* sh_w      = sm + 512;      // 8*256
    float* sh_cc     = sm + 2560;     // 8 (+pad)
    float* sh_scores = sm + 2576;     // 8*1024
    float* sh_hbar   = sm + 10768;    // 8*256
    float* sh_attn   = sm + 12816;    // 256
    float* sh_y      = sm + 13072;    // 256  -> total 13328 floats

    int b = blockIdx.x, tid = threadIdx.x, wid = tid >> 5, lane = tid & 31;
    const float* hb = g_h1 + (size_t)b * SQ * HH;

    sh_hlast[tid] = hb[(size_t)(SQ - 1) * HH + tid];
    __syncthreads();

    for (int j = 0; j < 32; j++) {
        int n = wid * 32 + j;
        float acc = 0.f;
#pragma unroll
        for (int i = 0; i < 8; i++)
            acc += Wq[(size_t)n * HH + lane + 32 * i] * sh_hlast[lane + 32 * i];
        acc = warp_sum(acc);
        if (lane == 0) sh_q[n] = acc + bq[n];
    }
    __syncthreads();

    {
        float v = sh_q[wid * 32 + lane] * bk[wid * 32 + lane];
        v = warp_sum(v);
        if (lane == 0) sh_cc[wid] = v;
    }
    {
        float acc[8] = {0.f, 0.f, 0.f, 0.f, 0.f, 0.f, 0.f, 0.f};
        for (int rr = 0; rr < HH; rr++) {
            float wkv = Wk[(size_t)rr * HH + tid];
            acc[rr >> 5] += wkv * sh_q[rr];
        }
#pragma unroll
        for (int h = 0; h < 8; h++) sh_w[h * HH + tid] = acc[h];
    }
    __syncthreads();

    const float L2D = -0.07400058144377693f;      // log2(0.95)
    const float ISQ = 0.17677669529663687f;       // 1/sqrt(32)
    for (int t = 0; t < SQ; t++) {
        const float* hr = hb + (size_t)t * HH;
        float acc = 0.f;
#pragma unroll
        for (int i = 0; i < 8; i++)
            acc += sh_w[wid * HH + lane + 32 * i] * hr[lane + 32 * i];
        acc = warp_sum(acc);
        if (lane == 0) {
            float sc = (acc + sh_cc[wid]) * ISQ;
            sc *= exp2f((float)(SQ - 1 - t) * L2D);
            sh_scores[wid * SQ + t] = sc;
        }
    }
    __syncwarp();

    float mx = -1e30f;
    for (int t = lane; t < SQ; t += 32) mx = fmaxf(mx, sh_scores[wid * SQ + t]);
    mx = warp_max(mx);
    float sum = 0.f;
    for (int t = lane; t < SQ; t += 32) {
        float e = __expf(sh_scores[wid * SQ + t] - mx);
        sh_scores[wid * SQ + t] = e;
        sum += e;
    }
    sum = warp_sum(sum);
    float inv = 1.f / sum;
    for (int t = lane; t < SQ; t += 32) sh_scores[wid * SQ + t] *= inv;
    __syncwarp();

    float hb8[8] = {0.f, 0.f, 0.f, 0.f, 0.f, 0.f, 0.f, 0.f};
    for (int t = 0; t < SQ; t++) {
        float pv = sh_scores[wid * SQ + t];
        const float* hr = hb + (size_t)t * HH;
#pragma unroll
        for (int i = 0; i < 8; i++) hb8[i] += pv * hr[lane + 32 * i];
    }
#pragma unroll
    for (int i = 0; i < 8; i++) sh_hbar[wid * HH + lane + 32 * i] = hb8[i];
    __syncwarp();

    for (int d = 0; d < 32; d++) {
        int row = wid * 32 + d;
        float acc = 0.f;
#pragma unroll
        for (int i = 0; i < 8; i++)
            acc += Wv[(size_t)row * HH + lane + 32 * i] * sh_hbar[wid * HH + lane + 32 * i];
        acc = warp_sum(acc);
        if (lane == 0) sh_attn[row] = acc + bv[row];
    }
    __syncthreads();

    for (int j = 0; j < 32; j++) {
        int n = wid * 32 + j;
        float acc = 0.f;
#pragma unroll
        for (int i = 0; i < 8; i++)
            acc += Wo[(size_t)n * HH + lane + 32 * i] * sh_attn[lane + 32 * i];
        acc = warp_sum(acc);
        if (lane == 0) sh_y[n] = acc + bo[n];
    }
    __syncthreads();

    if (tid < 5) {
        float a = 0.f;
        for (int k = 0; k < HH; k++) a += Wm[tid * HH + k] * sh_y[k];
        outp[b * 5 + tid] = a + bm[tid];
    } else if (tid >= 32 && tid < 37) {
        int j = tid - 32;
        float a = 0.f;
        for (int k = 0; k < HH; k++) a += Wvr[j * HH + k] * sh_y[k];
        outp[BBATCH * 5 + b * 5 + j] = a + bvr[j];
    }
}

// ---------------- launch ----------------------------------------------------
extern "C" void kernel_launch(void* const* d_in, const int* in_sizes, int n_in,
                              void* d_out, int out_size)
{
    const float* x    = (const float*)d_in[0];
    const float* Wih0 = (const float*)d_in[1];
    const float* Whh0 = (const float*)d_in[2];
    const float* bih0 = (const float*)d_in[3];
    const float* bhh0 = (const float*)d_in[4];
    const float* Wih1 = (const float*)d_in[5];
    const float* Whh1 = (const float*)d_in[6];
    const float* bih1 = (const float*)d_in[7];
    const float* bhh1 = (const float*)d_in[8];
    const float* Wq   = (const float*)d_in[9];
    const float* bq   = (const float*)d_in[10];
    const float* Wk   = (const float*)d_in[11];
    const float* bk   = (const float*)d_in[12];
    const float* Wv   = (const float*)d_in[13];
    const float* bv   = (const float*)d_in[14];
    const float* Wo   = (const float*)d_in[15];
    const float* bo   = (const float*)d_in[16];
    const float* Wm   = (const float*)d_in[17];
    const float* bm   = (const float*)d_in[18];
    const float* Wvr  = (const float*)d_in[19];
    const float* bvr  = (const float*)d_in[20];
    float* outp = (float*)d_out;

    (void)in_sizes; (void)n_in; (void)out_size;

    cudaFuncSetAttribute(head_kernel, cudaFuncAttributeMaxDynamicSharedMemorySize, 13328 * 4);

    dim3 ggrid(8, 128);   // N/128, M/128

    // layer 0 input projection: x (16384 x 32) @ W_ih0^T + b_ih0 + b_hh0
    gemm_xproj_kernel<<<ggrid, 256>>>(x, Wih0, bih0, bhh0, 32, 0);

    // cluster launch config for the recurrence (16 clusters of 8 CTAs)
    cudaLaunchConfig_t cfg = {};
    cfg.gridDim = dim3(128, 1, 1);
    cfg.blockDim = dim3(256, 1, 1);
    cfg.dynamicSmemBytes = 0;
    cudaLaunchAttribute at[1];
    at[0].id = cudaLaunchAttributeClusterDimension;
    at[0].val.clusterDim.x = 8;
    at[0].val.clusterDim.y = 1;
    at[0].val.clusterDim.z = 1;
    cfg.attrs = at;
    cfg.numAttrs = 1;
    cfg.stream = 0;

    cudaLaunchKernelEx(&cfg, lstm_rec_kernel, Whh0, 0);

    // layer 1 input projection: h0 (16384 x 256) @ W_ih1^T + b_ih1 + b_hh1
    gemm_xproj_kernel<<<ggrid, 256>>>(nullptr, Wih1, bih1, bhh1, 256, 1);

    cudaLaunchKernelEx(&cfg, lstm_rec_kernel, Whh1, 1);

    // decayed attention on last query + output heads
    head_kernel<<<BBATCH, 256, 13328 * 4>>>(Wq, bq, Wk, bk, Wv, bv, Wo, bo,
                                            Wm, bm, Wvr, bvr, outp);
}

// round 16
// speedup vs baseline: 1.7805x; 1.1980x over previous
#include <cuda_runtime.h>
#include <math.h>

#define SQ   1024
#define HH   256
#define BBATCH 16
#define G4   1024   /* 4*H */

typedef unsigned long long ull;

// ---------------- scratch (static device globals: allocation-free) ----------
__device__ float g_xproj[BBATCH * SQ * G4];   // 64 MB, reused for both layers
__device__ float g_h0[BBATCH * SQ * HH];      // 16 MB
__device__ float g_h1[BBATCH * SQ * HH];      // 16 MB
__device__ float g_attn[BBATCH * HH];         // attention output (pre-Wo)

// ---------------- helpers ----------------------------------------------------
__device__ __forceinline__ float warp_sum(float v) {
#pragma unroll
    for (int o = 16; o > 0; o >>= 1) v += __shfl_xor_sync(0xffffffffu, v, o);
    return v;
}
__device__ __forceinline__ float warp_max(float v) {
#pragma unroll
    for (int o = 16; o > 0; o >>= 1) v = fmaxf(v, __shfl_xor_sync(0xffffffffu, v, o));
    return v;
}
__device__ __forceinline__ unsigned smem_u32(const void* p) {
    unsigned a;
    asm("{ .reg .u64 t; cvta.to.shared.u64 t, %1; cvt.u32.u64 %0, t; }" : "=r"(a) : "l"(p));
    return a;
}
__device__ __forceinline__ unsigned ctarank() {
    unsigned r; asm("mov.u32 %0, %%cluster_ctarank;" : "=r"(r)); return r;
}
__device__ __forceinline__ void cluster_sync_() {
    asm volatile("barrier.cluster.arrive.aligned;\n\tbarrier.cluster.wait.aligned;" ::: "memory");
}
__device__ __forceinline__ unsigned mapa_u32(unsigned laddr, unsigned rank) {
    unsigned ra;
    asm("mapa.shared::cluster.u32 %0, %1, %2;" : "=r"(ra) : "r"(laddr), "r"(rank));
    return ra;
}
__device__ __forceinline__ void dsmem_st1(unsigned raddr, float v) {
    asm volatile("st.shared::cluster.b32 [%0], %1;"
                 :: "r"(raddr), "r"(__float_as_uint(v)) : "memory");
}
#define FMA2(acc, a, b) asm volatile("fma.rn.f32x2 %0, %1, %2, %0;" : "+l"(acc) : "l"(a), "l"(b))
__device__ __forceinline__ float2 unpack2(ull u) {
    float2 f; asm("mov.b64 {%0, %1}, %2;" : "=f"(f.x), "=f"(f.y) : "l"(u)); return f;
}
__device__ __forceinline__ ull pack2(float x, float y) {
    ull r; asm("mov.b64 %0, {%1, %2};" : "=l"(r) : "f"(x), "f"(y)); return r;
}
__device__ __forceinline__ float ex2f_(float x) {
    float r; asm("ex2.approx.ftz.f32 %0, %1;" : "=f"(r) : "f"(x)); return r;
}
__device__ __forceinline__ float rcpf_(float x) {
    float r; asm("rcp.approx.ftz.f32 %0, %1;" : "=f"(r) : "f"(x)); return r;
}
__device__ __forceinline__ float fast_sig(float x) {
    return rcpf_(1.f + ex2f_(-1.4426950408889634f * x));
}
__device__ __forceinline__ float fast_tanh(float x) {
    x = fminf(fmaxf(x, -15.f), 15.f);
    float u = ex2f_(2.8853900817779268f * x);
    return (u - 1.f) * rcpf_(u + 1.f);
}

// ---------------- GEMM: out[m,n] = sum_k X[m,k]*W[n,k] + b1[n] + b2[n] ------
// M=16384, N=1024 fixed; K in {32, 256}. 128x128 block tile, 8x8 per thread,
// packed fma.rn.f32x2 inner product.
__global__ void __launch_bounds__(256)
gemm_xproj_kernel(const float* __restrict__ Xext, const float* __restrict__ W,
                  const float* __restrict__ b1, const float* __restrict__ b2,
                  int K, int use_h0)
{
    __shared__ __align__(16) float As[16][132];
    __shared__ __align__(16) float Bs[16][132];
    const float* X = use_h0 ? g_h0 : Xext;
    float* out = g_xproj;
    const int N = G4;

    int bm = blockIdx.y * 128, bn = blockIdx.x * 128;
    int tid = threadIdx.x;
    int lr = tid >> 2, lc = (tid & 3) << 2;
    int tm = (tid >> 4) << 3, tn = (tid & 15) << 3;

    ull acc[8][4];
#pragma unroll
    for (int i = 0; i < 8; i++)
#pragma unroll
        for (int j = 0; j < 4; j++) acc[i][j] = 0ull;

    for (int k0 = 0; k0 < K; k0 += 16) {
        float4 a0 = *(const float4*)&X[(size_t)(bm + lr) * K + k0 + lc];
        float4 a1 = *(const float4*)&X[(size_t)(bm + lr + 64) * K + k0 + lc];
        float4 w0 = *(const float4*)&W[(size_t)(bn + lr) * K + k0 + lc];
        float4 w1 = *(const float4*)&W[(size_t)(bn + lr + 64) * K + k0 + lc];
        __syncthreads();
        As[lc + 0][lr] = a0.x; As[lc + 1][lr] = a0.y; As[lc + 2][lr] = a0.z; As[lc + 3][lr] = a0.w;
        As[lc + 0][lr + 64] = a1.x; As[lc + 1][lr + 64] = a1.y; As[lc + 2][lr + 64] = a1.z; As[lc + 3][lr + 64] = a1.w;
        Bs[lc + 0][lr] = w0.x; Bs[lc + 1][lr] = w0.y; Bs[lc + 2][lr] = w0.z; Bs[lc + 3][lr] = w0.w;
        Bs[lc + 0][lr + 64] = w1.x; Bs[lc + 1][lr + 64] = w1.y; Bs[lc + 2][lr + 64] = w1.z; Bs[lc + 3][lr + 64] = w1.w;
        __syncthreads();
#pragma unroll
        for (int k = 0; k < 16; k++) {
            float av[8], bv[8];
            *(float4*)&av[0] = *(const float4*)&As[k][tm];
            *(float4*)&av[4] = *(const float4*)&As[k][tm + 4];
            *(float4*)&bv[0] = *(const float4*)&Bs[k][tn];
            *(float4*)&bv[4] = *(const float4*)&Bs[k][tn + 4];
            ull b2v[4];
#pragma unroll
            for (int j = 0; j < 4; j++) b2v[j] = pack2(bv[2 * j], bv[2 * j + 1]);
#pragma unroll
            for (int i = 0; i < 8; i++) {
                ull a2 = pack2(av[i], av[i]);
#pragma unroll
                for (int j = 0; j < 4; j++)
                    FMA2(acc[i][j], a2, b2v[j]);
            }
        }
    }
    float bias8[8];
#pragma unroll
    for (int j = 0; j < 8; j++) bias8[j] = b1[bn + tn + j] + b2[bn + tn + j];
#pragma unroll
    for (int i = 0; i < 8; i++) {
        float o[8];
#pragma unroll
        for (int j = 0; j < 4; j++) {
            float2 e = unpack2(acc[i][j]);
            o[2 * j] = e.x + bias8[2 * j];
            o[2 * j + 1] = e.y + bias8[2 * j + 1];
        }
        float* dst = &out[(size_t)(bm + tm + i) * N + bn + tn];
        *(float4*)&dst[0] = make_float4(o[0], o[1], o[2], o[3]);
        *(float4*)&dst[4] = make_float4(o[4], o[5], o[6], o[7]);
    }
}

// ---------------- LSTM recurrence: 8-CTA cluster per batch sample ----------
// R7 VERBATIM — best measured (1897 us/kernel). cluster.sync per step,
// push model: each lane one scalar st.shared::cluster of its own unit;
// gates computed redundantly by all warps; LDS.128 matvec; fast activations.
__global__ void __launch_bounds__(256, 1)
lstm_rec_kernel(const float* __restrict__ Whh, int layer)
{
    __shared__ __align__(16) float sh_h[2][HH];
    __shared__ __align__(8) float sh_part[128][2];

    float* hout = layer ? g_h1 : g_h0;
    int tid = threadIdx.x;
    int r = tid & 127;
    int half = tid >> 7;
    int wid = tid >> 5, lane = tid & 31;
    unsigned rank = ctarank();
    int b = blockIdx.x >> 3;
    int gt = r >> 5, uo = r & 31;
    int G = gt * HH + (int)rank * 32 + uo;

    ull w[64];
    {
        const ull* wp = reinterpret_cast<const ull*>(Whh + (size_t)G * HH + half * 128);
#pragma unroll
        for (int i = 0; i < 64; i++) w[i] = wp[i];
    }

    sh_h[0][tid & 255] = 0.f;
    sh_h[1][tid & 255] = 0.f;
    __syncthreads();
    cluster_sync_();   // zeroed buffers visible cluster-wide

    // warp w services destination CTA w; this lane owns unit rank*32+lane
    unsigned dest = (unsigned)wid;
    int unit = (int)rank * 32 + lane;
    unsigned rdst0 = mapa_u32(smem_u32(&sh_h[0][unit]), dest);
    unsigned rdst1 = mapa_u32(smem_u32(&sh_h[1][unit]), dest);

    const float* xp = g_xproj + (size_t)b * SQ * G4 + G;
    float xv = (half == 0) ? xp[0] : 0.f;
    float creg = 0.f;

    int p = 0;
    for (int t = 0; t < SQ; t++) {
        float xnext = (half == 0 && t + 1 < SQ) ? xp[(size_t)(t + 1) * G4] : 0.f;

        // matvec: 32 LDS.128 + 64 FFMA2 (warp-uniform broadcast loads)
        const ulonglong2* h2 = reinterpret_cast<const ulonglong2*>(&sh_h[p][half * 128]);
        ull a0 = 0ull, a1 = 0ull, a2 = 0ull, a3 = 0ull;
#pragma unroll
        for (int q = 0; q < 32; q += 2) {
            ulonglong2 hv0 = h2[q];
            ulonglong2 hv1 = h2[q + 1];
            FMA2(a0, w[2 * q + 0], hv0.x);
            FMA2(a1, w[2 * q + 1], hv0.y);
            FMA2(a2, w[2 * q + 2], hv1.x);
            FMA2(a3, w[2 * q + 3], hv1.y);
        }
        float2 f0 = unpack2(a0), f1 = unpack2(a1), f2 = unpack2(a2), f3 = unpack2(a3);
        float s = ((f0.x + f0.y) + (f1.x + f1.y)) + ((f2.x + f2.y) + (f3.x + f3.y));
        sh_part[r][half] = (half == 0) ? (s + xv) : s;
        __syncthreads();

        // gates: every warp computes all 32 of this CTA's units (lane = unit)
        float2 pi = *(const float2*)sh_part[lane];
        float2 pf = *(const float2*)sh_part[32 + lane];
        float2 pg = *(const float2*)sh_part[64 + lane];
        float2 po = *(const float2*)sh_part[96 + lane];
        float iv = fast_sig(pi.x + pi.y);
        float fv = fast_sig(pf.x + pf.y);
        float gv = fast_tanh(pg.x + pg.y);
        float ov = fast_sig(po.x + po.y);
        creg = fv * creg + iv * gv;
        float hv = ov * fast_tanh(creg);

        // broadcast: one scalar remote store per lane into dest's write buffer
        dsmem_st1(p ? rdst0 : rdst1, hv);
        if (wid == 0)
            hout[((size_t)b * SQ + t) * HH + unit] = hv;

        // release stores + protect sh_part/sh_h reuse (R7-proven)
        cluster_sync_();
        xv = xnext;
        p ^= 1;
    }
}

// ---------------- head part 1: per-(sample, head) attention ------------------
// 128 CTAs (b = blockIdx>>3, h = blockIdx&7), 256 threads. Both 1024-step
// passes distributed across all 8 warps (t strided by warp) instead of the
// old single-warp-per-head serial loops.
__global__ void __launch_bounds__(256)
head1_kernel(const float* __restrict__ Wq, const float* __restrict__ bq,
             const float* __restrict__ Wk, const float* __restrict__ bk,
             const float* __restrict__ Wv, const float* __restrict__ bv)
{
    __shared__ __align__(16) float sh_hlast[HH];
    __shared__ __align__(16) float sh_q[32];
    __shared__ __align__(16) float sh_w[HH];
    __shared__ __align__(16) float sh_p[SQ];
    __shared__ __align__(16) float sh_hb[8][HH];
    __shared__ __align__(16) float sh_hbar[HH];
    __shared__ float sh_red[8];
    __shared__ float sh_cc;

    int bidx = blockIdx.x;
    int b = bidx >> 3, h = bidx & 7;
    int tid = threadIdx.x, wid = tid >> 5, lane = tid & 31;
    const float* hb = g_h1 + (size_t)b * SQ * HH;

    sh_hlast[tid] = hb[(size_t)(SQ - 1) * HH + tid];
    __syncthreads();

    // q[d] for d in [0,32): warp wid does rows wid*4..wid*4+3
#pragma unroll
    for (int j = 0; j < 4; j++) {
        int d = wid * 4 + j;
        int row = h * 32 + d;
        float acc = 0.f;
#pragma unroll
        for (int i = 0; i < 8; i++)
            acc += Wq[(size_t)row * HH + lane + 32 * i] * sh_hlast[lane + 32 * i];
        acc = warp_sum(acc);
        if (lane == 0) sh_q[d] = acc + bq[row];
    }
    __syncthreads();

    // cc = q_h · bk_h  (warp 0)
    if (wid == 0) {
        float v = sh_q[lane] * bk[h * 32 + lane];
        v = warp_sum(v);
        if (lane == 0) sh_cc = v;
    }
    // w[k] = sum_d q[d] * Wk[h*32+d, k]   (thread k = tid; coalesced rows)
    {
        float acc = 0.f;
#pragma unroll 8
        for (int d = 0; d < 32; d++)
            acc += Wk[(size_t)(h * 32 + d) * HH + tid] * sh_q[d];
        sh_w[tid] = acc;
    }
    __syncthreads();

    // pass 1: scores, t strided across 8 warps
    const float L2D = -0.07400058144377693f;      // log2(0.95)
    const float ISQ = 0.17677669529663687f;       // 1/sqrt(32)
    float cc = sh_cc;
    for (int t = wid; t < SQ; t += 8) {
        const float* hr = hb + (size_t)t * HH;
        float acc = 0.f;
#pragma unroll
        for (int i = 0; i < 8; i++)
            acc += sh_w[lane + 32 * i] * hr[lane + 32 * i];
        acc = warp_sum(acc);
        if (lane == 0)
            sh_p[t] = (acc + cc) * ISQ * exp2f((float)(SQ - 1 - t) * L2D);
    }
    __syncthreads();

    // block softmax over sh_p[1024]
    float mx = -1e30f;
    for (int t = tid; t < SQ; t += 256) mx = fmaxf(mx, sh_p[t]);
    mx = warp_max(mx);
    if (lane == 0) sh_red[wid] = mx;
    __syncthreads();
    mx = sh_red[0];
#pragma unroll
    for (int i = 1; i < 8; i++) mx = fmaxf(mx, sh_red[i]);
    float sum = 0.f;
    for (int t = tid; t < SQ; t += 256) {
        float e = __expf(sh_p[t] - mx);
        sh_p[t] = e;
        sum += e;
    }
    sum = warp_sum(sum);
    __syncthreads();
    if (lane == 0) sh_red[wid] = sum;
    __syncthreads();
    sum = sh_red[0];
#pragma unroll
    for (int i = 1; i < 8; i++) sum += sh_red[i];
    float inv = 1.f / sum;
    __syncthreads();

    // pass 2: hbar = sum_t p_t * h_t, t strided across 8 warps
    float acc8[8] = {0.f, 0.f, 0.f, 0.f, 0.f, 0.f, 0.f, 0.f};
    for (int t = wid; t < SQ; t += 8) {
        float pv = sh_p[t];
        const float* hr = hb + (size_t)t * HH;
#pragma unroll
        for (int i = 0; i < 8; i++) acc8[i] += pv * hr[lane + 32 * i];
    }
#pragma unroll
    for (int i = 0; i < 8; i++) sh_hb[wid][lane + 32 * i] = acc8[i];
    __syncthreads();
    {
        float v = 0.f;
#pragma unroll
        for (int wdx = 0; wdx < 8; wdx++) v += sh_hb[wdx][tid];
        sh_hbar[tid] = v * inv;
    }
    __syncthreads();

    // out_h[d] = Wv[h*32+d,:]·hbar + bv  (warp wid -> 4 rows)
#pragma unroll
    for (int j = 0; j < 4; j++) {
        int d = wid * 4 + j;
        int row = h * 32 + d;
        float acc = 0.f;
#pragma unroll
        for (int i = 0; i < 8; i++)
            acc += Wv[(size_t)row * HH + lane + 32 * i] * sh_hbar[lane + 32 * i];
        acc = warp_sum(acc);
        if (lane == 0) g_attn[b * HH + row] = acc + bv[row];
    }
}

// ---------------- head part 2: Wo projection + mean/log_var ------------------
__global__ void __launch_bounds__(256)
head2_kernel(const float* __restrict__ Wo, const float* __restrict__ bo,
             const float* __restrict__ Wm, const float* __restrict__ bm,
             const float* __restrict__ Wvr, const float* __restrict__ bvr,
             float* __restrict__ outp)
{
    __shared__ __align__(16) float sh_attn[HH];
    __shared__ __align__(16) float sh_y[HH];

    int b = blockIdx.x, tid = threadIdx.x, wid = tid >> 5, lane = tid & 31;

    sh_attn[tid] = g_attn[b * HH + tid];
    __syncthreads();

    // y = Wo·attn + bo (warp wid -> rows [32wid, 32wid+32))
    for (int j = 0; j < 32; j++) {
        int n = wid * 32 + j;
        float acc = 0.f;
#pragma unroll
        for (int i = 0; i < 8; i++)
            acc += Wo[(size_t)n * HH + lane + 32 * i] * sh_attn[lane + 32 * i];
        acc = warp_sum(acc);
        if (lane == 0) sh_y[n] = acc + bo[n];
    }
    __syncthreads();

    if (tid < 5) {
        float a = 0.f;
        for (int k = 0; k < HH; k++) a += Wm[tid * HH + k] * sh_y[k];
        outp[b * 5 + tid] = a + bm[tid];
    } else if (tid >= 32 && tid < 37) {
        int j = tid - 32;
        float a = 0.f;
        for (int k = 0; k < HH; k++) a += Wvr[j * HH + k] * sh_y[k];
        outp[BBATCH * 5 + b * 5 + j] = a + bvr[j];
    }
}

// ---------------- launch ----------------------------------------------------
extern "C" void kernel_launch(void* const* d_in, const int* in_sizes, int n_in,
                              void* d_out, int out_size)
{
    const float* x    = (const float*)d_in[0];
    const float* Wih0 = (const float*)d_in[1];
    const float* Whh0 = (const float*)d_in[2];
    const float* bih0 = (const float*)d_in[3];
    const float* bhh0 = (const float*)d_in[4];
    const float* Wih1 = (const float*)d_in[5];
    const float* Whh1 = (const float*)d_in[6];
    const float* bih1 = (const float*)d_in[7];
    const float* bhh1 = (const float*)d_in[8];
    const float* Wq   = (const float*)d_in[9];
    const float* bq   = (const float*)d_in[10];
    const float* Wk   = (const float*)d_in[11];
    const float* bk   = (const float*)d_in[12];
    const float* Wv   = (const float*)d_in[13];
    const float* bv   = (const float*)d_in[14];
    const float* Wo   = (const float*)d_in[15];
    const float* bo   = (const float*)d_in[16];
    const float* Wm   = (const float*)d_in[17];
    const float* bm   = (const float*)d_in[18];
    const float* Wvr  = (const float*)d_in[19];
    const float* bvr  = (const float*)d_in[20];
    float* outp = (float*)d_out;

    (void)in_sizes; (void)n_in; (void)out_size;

    dim3 ggrid(8, 128);   // N/128, M/128

    // layer 0 input projection: x (16384 x 32) @ W_ih0^T + b_ih0 + b_hh0
    gemm_xproj_kernel<<<ggrid, 256>>>(x, Wih0, bih0, bhh0, 32, 0);

    // cluster launch config for the recurrence (16 clusters of 8 CTAs)
    cudaLaunchConfig_t cfg = {};
    cfg.gridDim = dim3(128, 1, 1);
    cfg.blockDim = dim3(256, 1, 1);
    cfg.dynamicSmemBytes = 0;
    cudaLaunchAttribute at[1];
    at[0].id = cudaLaunchAttributeClusterDimension;
    at[0].val.clusterDim.x = 8;
    at[0].val.clusterDim.y = 1;
    at[0].val.clusterDim.z = 1;
    cfg.attrs = at;
    cfg.numAttrs = 1;
    cfg.stream = 0;

    cudaLaunchKernelEx(&cfg, lstm_rec_kernel, Whh0, 0);

    // layer 1 input projection: h0 (16384 x 256) @ W_ih1^T + b_ih1 + b_hh1
    gemm_xproj_kernel<<<ggrid, 256>>>(nullptr, Wih1, bih1, bhh1, 256, 1);

    cudaLaunchKernelEx(&cfg, lstm_rec_kernel, Whh1, 1);

    // decayed attention on last query: per-(sample,head) CTAs, then tail
    head1_kernel<<<128, 256>>>(Wq, bq, Wk, bk, Wv, bv);
    head2_kernel<<<BBATCH, 256>>>(Wo, bo, Wm, bm, Wvr, bvr, outp);
}